// round 16
// baseline (speedup 1.0000x reference)
#include <cuda_runtime.h>
#include <cuda_fp16.h>
#include <math.h>
#include <stdint.h>

#define Bb 8
#define IN_N 8
#define OUT_N 8
#define SEQ 256
#define FEAT 64
#define NCg 99
#define KSZ 15

// ---------------- scratch ----------------
__device__ float g_mu[Bb*IN_N*FEAT];
__device__ float g_rinv[Bb*IN_N*FEAT];
__device__ float g_epart[Bb*IN_N*8*OUT_N];
__device__ __half g_acth[Bb*IN_N*OUT_N*SEQ*FEAT];   // 16.8 MB
__device__ float g_comb[Bb*OUT_N*SEQ*FEAT];
__device__ float g_xn [Bb*OUT_N*SEQ*FEAT];
__device__ float g_pS [Bb*IN_N*SEQ];
__device__ float g_pS2[Bb*IN_N*SEQ];
__device__ float g_H[Bb*4*SEQ*SEQ];                  // 8 MB
__device__ __half g_rawh[OUT_N*Bb*SEQ*SEQ];          // 8 MB, final attn weights

#define OFF_PROJ (Bb*OUT_N*SEQ*FEAT)

// ---------------- helpers ----------------
__device__ __forceinline__ void basis4(float u, float* bv, int* ci) {
    int m = (int)floorf(u);
    #pragma unroll
    for (int k = 0; k < 4; k++) {
        int c = m - 1 + k;
        float val = 0.f;
        if (c >= 0 && c < NCg) {
            float d  = fabsf(u - (float)c);
            float r2 = fmaxf(2.f - d, 0.f);
            float r1 = fmaxf(1.f - d, 0.f);
            val = r2*r2*r2*(1.f/6.f) - r1*r1*r1*(4.f/6.f);
        }
        ci[k] = min(max(c, 0), NCg - 1);
        bv[k] = val;
    }
}
__device__ __forceinline__ void maskmult(int bi, int o, const float* tau, float tv,
                                         float* mask, float* mult) {
    float e = 0.f;
    #pragma unroll
    for (int st = 0; st < 8; st++) e += g_epart[(bi*8+st)*8+o];
    float es = sqrtf(e * (1.f/16384.f) + 1e-8f);
    float ta = fabsf(tau[(bi & 7) * 8 + o]);
    *mask = 1.f / (1.f + expf(-(es - ta) / tv));
    *mult = es / (ta + 1e-8f);
}

// ---------------- K_H: H_g = P_{2g} @ P_{2g+1}^T (fp16 mma, fp32 out) ----------------
#define HPAD 72
__global__ void __launch_bounds__(256) k_H(const float* __restrict__ proj) {
    __shared__ __half sAH[128*HPAD];
    __shared__ __half sBH[128*HPAD];
    int bx = blockIdx.x;
    int b = bx >> 4, g = (bx >> 2) & 3, tile = bx & 3;
    int m0 = (tile >> 1)*128, n0 = (tile & 1)*128;
    const float* A  = proj + ((size_t)(b*8 + 2*g  ))*SEQ*FEAT;
    const float* Bp = proj + ((size_t)(b*8 + 2*g+1))*SEQ*FEAT;
    int tid = threadIdx.x, wid = tid >> 5, lane = tid & 31;
    #pragma unroll
    for (int l = 0; l < 8; l++) {
        int idx = tid + l*256;
        int row = idx >> 4, c4 = idx & 15;
        float4 va = *(const float4*)&A[(size_t)(m0+row)*FEAT + c4*4];
        *(__half2*)&sAH[row*HPAD + c4*4]     = __floats2half2_rn(va.x, va.y);
        *(__half2*)&sAH[row*HPAD + c4*4 + 2] = __floats2half2_rn(va.z, va.w);
        float4 vb = *(const float4*)&Bp[(size_t)(n0+row)*FEAT + c4*4];
        *(__half2*)&sBH[row*HPAD + c4*4]     = __floats2half2_rn(vb.x, vb.y);
        *(__half2*)&sBH[row*HPAD + c4*4 + 2] = __floats2half2_rn(vb.z, vb.w);
    }
    __syncthreads();

    int wm = (wid & 3)*32, wn = (wid >> 2)*64;
    int gr = lane >> 2, tg = lane & 3;
    float acc[2][8][4];
    #pragma unroll
    for (int i = 0; i < 2; i++)
        #pragma unroll
        for (int n = 0; n < 8; n++)
            #pragma unroll
            for (int q = 0; q < 4; q++) acc[i][n][q] = 0.f;

    #pragma unroll
    for (int ks = 0; ks < 4; ks++) {
        int kk = ks * 16;
        uint32_t a[2][4];
        #pragma unroll
        for (int i = 0; i < 2; i++) {
            int r = wm + i*16 + gr;
            a[i][0] = *(const uint32_t*)&sAH[r*HPAD + kk + 2*tg];
            a[i][1] = *(const uint32_t*)&sAH[(r+8)*HPAD + kk + 2*tg];
            a[i][2] = *(const uint32_t*)&sAH[r*HPAD + kk + 8 + 2*tg];
            a[i][3] = *(const uint32_t*)&sAH[(r+8)*HPAD + kk + 8 + 2*tg];
        }
        uint32_t bfr[8][2];
        #pragma unroll
        for (int n = 0; n < 8; n++) {
            int cc = wn + n*8 + gr;
            bfr[n][0] = *(const uint32_t*)&sBH[cc*HPAD + kk + 2*tg];
            bfr[n][1] = *(const uint32_t*)&sBH[cc*HPAD + kk + 8 + 2*tg];
        }
        #pragma unroll
        for (int i = 0; i < 2; i++)
            #pragma unroll
            for (int n = 0; n < 8; n++) {
                asm volatile(
                    "mma.sync.aligned.m16n8k16.row.col.f32.f16.f16.f32 "
                    "{%0,%1,%2,%3}, {%4,%5,%6,%7}, {%8,%9}, {%0,%1,%2,%3};"
                    : "+f"(acc[i][n][0]), "+f"(acc[i][n][1]),
                      "+f"(acc[i][n][2]), "+f"(acc[i][n][3])
                    : "r"(a[i][0]), "r"(a[i][1]), "r"(a[i][2]), "r"(a[i][3]),
                      "r"(bfr[n][0]), "r"(bfr[n][1]));
            }
    }
    float* Hg = g_H + ((size_t)(b*4+g))*SEQ*SEQ;
    #pragma unroll
    for (int i = 0; i < 2; i++)
        #pragma unroll
        for (int n = 0; n < 8; n++) {
            int r = m0 + wm + i*16 + gr;
            int c = n0 + wn + n*8 + 2*tg;
            float2 o0 = {acc[i][n][0], acc[i][n][1]};
            float2 o1 = {acc[i][n][2], acc[i][n][3]};
            *(float2*)&Hg[(size_t)r*256 + c]     = o0;
            *(float2*)&Hg[(size_t)(r+8)*256 + c] = o1;
        }
}

// ---------------- K_statsP: x stats (bx<64) + proj row sums (bx>=64) ----------------
__global__ void k_statsP(const float* __restrict__ x, const float* __restrict__ proj) {
    int bx = blockIdx.x, tid = threadIdx.x;
    if (bx < 64) {
        int f = tid & 63, q = tid >> 6;
        const float* p = x + (size_t)bx * SEQ * FEAT;
        float s = 0.f, s2 = 0.f;
        for (int t = q*64; t < q*64+64; t++) { float v = p[t*64+f]; s += v; s2 = fmaf(v,v,s2); }
        __shared__ float ps[4][64], ps2[4][64];
        ps[q][f] = s; ps2[q][f] = s2; __syncthreads();
        if (q == 0) {
            float S  = ps[0][f]+ps[1][f]+ps[2][f]+ps[3][f];
            float S2 = ps2[0][f]+ps2[1][f]+ps2[2][f]+ps2[3][f];
            float mu = S * (1.f/256.f);
            float var = S2 * (1.f/256.f) - mu*mu;
            g_mu[bx*64+f] = mu;
            g_rinv[bx*64+f] = rsqrtf(var + 1e-5f);
        }
    } else {
        int bi = bx - 64;
        int w = tid >> 5, lane = tid & 31;
        const float* p = proj + (size_t)bi * SEQ * FEAT;
        for (int r = 0; r < 32; r++) {
            int s = w*32 + r;
            float2 v = *(const float2*)&p[(size_t)s*64 + lane*2];
            float sm = v.x + v.y, sq = v.x*v.x + v.y*v.y;
            for (int off = 16; off; off >>= 1) {
                sm += __shfl_xor_sync(0xffffffffu, sm, off);
                sq += __shfl_xor_sync(0xffffffffu, sq, off);
            }
            if (lane == 0) { g_pS[bi*256+s] = sm; g_pS2[bi*256+s] = sq; }
        }
    }
}

// ---------------- K_actE ----------------
__global__ void k_actE(const float* __restrict__ x, const float* __restrict__ sw,
                       const float* __restrict__ omiga) {
    int bx = blockIdx.x;
    int bi = bx >> 3, st = bx & 7, i = bi & 7;
    int tid = threadIdx.x;
    __shared__ float s_swT[NCg*8];
    __shared__ float s_om[8];
    __shared__ float s_mu[64], s_ri[64];
    __shared__ float wr[8][8];
    for (int t = tid; t < NCg*8; t += 256) {
        int c = t >> 3, o = t & 7;
        s_swT[t] = sw[i*OUT_N*NCg + o*NCg + c];
    }
    if (tid < 8) s_om[tid] = fabsf(omiga[i*8 + tid]);
    if (tid < 64) { s_mu[tid] = g_mu[bi*64+tid]; s_ri[tid] = g_rinv[bi*64+tid]; }
    __syncthreads();

    float eacc[8];
    #pragma unroll
    for (int o = 0; o < 8; o++) eacc[o] = 0.f;

    const float* xb = x + (size_t)bi * SEQ * FEAT + (size_t)st * 32 * FEAT;
    __half* ah = g_acth + (size_t)bi * OUT_N * SEQ * FEAT + (size_t)st * 32 * FEAT;
    #pragma unroll
    for (int it = 0; it < 4; it++) {
        int e = 2*tid + 512*it;
        int ff = e & 63;
        float2 xv = *(const float2*)&xb[e];
        float a0[8], a1[8];
        {
            float xn = (xv.x - s_mu[ff]) * s_ri[ff] * 0.5f;
            xn = fminf(fmaxf(xn, -0.99f), 0.99f);
            float bv[4]; int ci[4];
            basis4((xn + 1.f) * 49.f, bv, ci);
            #pragma unroll
            for (int o = 0; o < 8; o++) a0[o] = s_om[o] * xv.x;
            #pragma unroll
            for (int k = 0; k < 4; k++) {
                float4 w0 = *(const float4*)&s_swT[ci[k]*8];
                float4 w1 = *(const float4*)&s_swT[ci[k]*8 + 4];
                a0[0]=fmaf(bv[k],w0.x,a0[0]); a0[1]=fmaf(bv[k],w0.y,a0[1]);
                a0[2]=fmaf(bv[k],w0.z,a0[2]); a0[3]=fmaf(bv[k],w0.w,a0[3]);
                a0[4]=fmaf(bv[k],w1.x,a0[4]); a0[5]=fmaf(bv[k],w1.y,a0[5]);
                a0[6]=fmaf(bv[k],w1.z,a0[6]); a0[7]=fmaf(bv[k],w1.w,a0[7]);
            }
        }
        {
            float xn = (xv.y - s_mu[ff+1]) * s_ri[ff+1] * 0.5f;
            xn = fminf(fmaxf(xn, -0.99f), 0.99f);
            float bv[4]; int ci[4];
            basis4((xn + 1.f) * 49.f, bv, ci);
            #pragma unroll
            for (int o = 0; o < 8; o++) a1[o] = s_om[o] * xv.y;
            #pragma unroll
            for (int k = 0; k < 4; k++) {
                float4 w0 = *(const float4*)&s_swT[ci[k]*8];
                float4 w1 = *(const float4*)&s_swT[ci[k]*8 + 4];
                a1[0]=fmaf(bv[k],w0.x,a1[0]); a1[1]=fmaf(bv[k],w0.y,a1[1]);
                a1[2]=fmaf(bv[k],w0.z,a1[2]); a1[3]=fmaf(bv[k],w0.w,a1[3]);
                a1[4]=fmaf(bv[k],w1.x,a1[4]); a1[5]=fmaf(bv[k],w1.y,a1[5]);
                a1[6]=fmaf(bv[k],w1.z,a1[6]); a1[7]=fmaf(bv[k],w1.w,a1[7]);
            }
        }
        #pragma unroll
        for (int o = 0; o < 8; o++) {
            eacc[o] = fmaf(a0[o], a0[o], fmaf(a1[o], a1[o], eacc[o]));
            *(__half2*)&ah[(size_t)o * SEQ * FEAT + e] = __floats2half2_rn(a0[o], a1[o]);
        }
    }
    #pragma unroll
    for (int o = 0; o < 8; o++)
        for (int off = 16; off; off >>= 1)
            eacc[o] += __shfl_xor_sync(0xffffffffu, eacc[o], off);
    int w = tid >> 5, lane = tid & 31;
    if (lane == 0)
        for (int o = 0; o < 8; o++) wr[w][o] = eacc[o];
    __syncthreads();
    if (tid < 8) {
        float sm = 0.f;
        for (int ww = 0; ww < 8; ww++) sm += wr[ww][tid];
        g_epart[bx*8 + tid] = sm;
    }
}

// ---------------- K_attn: raw-from-H + softmax -> attn fp16 (j-split, 512 blocks) ----------------
__global__ void __launch_bounds__(256) k_attn(const float* __restrict__ tau,
                                              const float* __restrict__ temp,
                                              const float* __restrict__ alphas,
                                              const float* __restrict__ betas) {
    int bx = blockIdx.x;            // b*64 + tile(8 rows)*2 + jhalf
    int b = bx >> 6;
    int rem = bx & 63;
    int s0 = (rem >> 1) * 8;
    int jh = (rem & 1) * 4;
    int tid = threadIdx.x;
    __shared__ float s_sc[8][8];
    __shared__ float s_w[4][4];
    __shared__ float s_mQ[4][264], s_rQ[4][264];
    __shared__ float s_mk[4][8], s_rk[4][8];
    __shared__ float s_be[4], s_al[4];

    float tv = fabsf(temp[0]) + 1e-4f;
    if (tid < 64) {
        float mk, ml;
        maskmult(b*8 + (tid>>3), tid & 7, tau, tv, &mk, &ml);
        s_sc[tid>>3][tid&7] = mk * ml;
    }
    if (tid < 4) { s_be[tid] = fabsf(betas[jh + tid]); s_al[tid] = fabsf(alphas[jh + tid]); }
    __syncthreads();
    if (tid < 16) {
        int j = tid >> 2, g = tid & 3;
        s_w[j][g] = s_sc[2*g][jh + j] * s_sc[2*g+1][jh + j];
    }
    for (int t = tid; t < 1024; t += 256) {
        int j = t >> 8, tt = t & 255;
        int jj = jh + j;
        float mK = 0.f, sK = 0.f, mQ = 0.f, sQ = 0.f;
        #pragma unroll
        for (int g = 0; g < 4; g++) {
            float cK = s_sc[2*g][jj], cQ = s_sc[2*g+1][jj];
            int iK = (b*8 + 2*g)*256 + tt, iQ = (b*8 + 2*g+1)*256 + tt;
            mK = fmaf(cK, g_pS[iK], mK);  sK = fmaf(cK*cK, g_pS2[iK], sK);
            mQ = fmaf(cQ, g_pS[iQ], mQ);  sQ = fmaf(cQ*cQ, g_pS2[iQ], sQ);
        }
        mK *= (1.f/256.f); mQ *= (1.f/256.f);
        float rK = rsqrtf(sK*(1.f/256.f) - mK*mK + 1e-5f);
        float rQ = rsqrtf(sQ*(1.f/256.f) - mQ*mQ + 1e-5f);
        int ti = tt + (tt >> 5);
        s_mQ[j][ti] = 256.f * mQ;
        s_rQ[j][ti] = rQ;
        if (tt >= s0 && tt < s0 + 8) { s_mk[j][tt-s0] = mK; s_rk[j][tt-s0] = rK; }
    }
    __syncthreads();

    int row = tid >> 5, lane = tid & 31;
    int tbase = lane * 8;
    float h[4][8];
    const float* Hb = g_H + (size_t)b*4*65536 + (size_t)(s0+row)*256 + tbase;
    #pragma unroll
    for (int g = 0; g < 4; g++) {
        float4 v0 = *(const float4*)&Hb[(size_t)g*65536];
        float4 v1 = *(const float4*)&Hb[(size_t)g*65536 + 4];
        h[g][0]=v0.x; h[g][1]=v0.y; h[g][2]=v0.z; h[g][3]=v0.w;
        h[g][4]=v1.x; h[g][5]=v1.y; h[g][6]=v1.z; h[g][7]=v1.w;
    }
    float inv = 1.f / (16.f * tv);
    int lq = lane >> 2;
    #pragma unroll
    for (int j = 0; j < 4; j++) {
        int jj = jh + j;
        float w0 = s_w[j][0], w1 = s_w[j][1], w2 = s_w[j][2], w3 = s_w[j][3];
        float mK = s_mk[j][row];
        float rKi = s_rk[j][row] * inv;
        float raw[8];
        float m = -1e30f;
        #pragma unroll
        for (int e = 0; e < 8; e++) {
            int ti = tbase + e + lq;
            float hs = w0*h[0][e] + w1*h[1][e] + w2*h[2][e] + w3*h[3][e];
            float r = (hs - mK * s_mQ[j][ti]) * s_rQ[j][ti] * rKi;
            raw[e] = r;
            m = fmaxf(m, r);
        }
        for (int off = 16; off; off >>= 1) m = fmaxf(m, __shfl_xor_sync(0xffffffffu, m, off));
        float sum = 0.f;
        #pragma unroll
        for (int e = 0; e < 8; e++) { raw[e] = __expf(raw[e] - m); sum += raw[e]; }
        for (int off = 16; off; off >>= 1) sum += __shfl_xor_sync(0xffffffffu, sum, off);
        float sc2 = s_be[j] / sum;
        float al = s_al[j];
        __half2 hv[4];
        #pragma unroll
        for (int e2 = 0; e2 < 4; e2++) {
            float va = raw[2*e2] * sc2;
            float vb = raw[2*e2+1] * sc2;
            int t0 = tbase + 2*e2;
            if (t0     == s0 + row) va += al;
            if (t0 + 1 == s0 + row) vb += al;
            hv[e2] = __floats2half2_rn(va, vb);
        }
        *(uint4*)&g_rawh[((size_t)(jj*8+b))*65536 + (size_t)(s0+row)*256 + tbase] = *(uint4*)hv;
    }
}

// ---------------- K_comb ----------------
__global__ void k_comb(const float* __restrict__ tau, const float* __restrict__ temp,
                       const float* __restrict__ ln_w, const float* __restrict__ ln_b) {
    int bx = blockIdx.x;
    int b = bx >> 8;
    int rem = bx & 255;
    int st = rem >> 2, jh = (rem & 3) * 2;
    int tid = threadIdx.x;
    int fp = tid & 31;
    int sl = tid >> 5;
    int s = st*4 + sl;
    __shared__ float s_mask[8][8];
    __shared__ float s_lnw[512], s_lnb[512];

    float tv = fabsf(temp[0]) + 1e-4f;
    if (tid < 64) {
        float mk, ml;
        maskmult(b*8 + (tid>>3), tid & 7, tau, tv, &mk, &ml);
        s_mask[tid>>3][tid&7] = mk;
    }
    for (int t = tid; t < 512; t += 128) { s_lnw[t] = ln_w[t]; s_lnb[t] = ln_b[t]; }
    __syncthreads();

    float2 comb[2];
    #pragma unroll
    for (int j = 0; j < 2; j++) { comb[j].x = 0.f; comb[j].y = 0.f; }

    size_t ebase = (size_t)s * 64 + 2*fp;
    #pragma unroll
    for (int i = 0; i < 8; i++) {
        const __half* ai = g_acth + ((size_t)(b*8+i)) * OUT_N * SEQ * FEAT
                         + (size_t)jh * SEQ * FEAT;
        #pragma unroll
        for (int j = 0; j < 2; j++) {
            float2 v = __half22float2(*(const __half2*)&ai[(size_t)j*SEQ*FEAT + ebase]);
            float mk = s_mask[i][jh + j];
            comb[j].x = fmaf(mk, v.x, comb[j].x);
            comb[j].y = fmaf(mk, v.y, comb[j].y);
        }
    }

    #pragma unroll
    for (int j = 0; j < 2; j++) {
        int jj = jh + j;
        float sm = comb[j].x + comb[j].y;
        float sq = comb[j].x*comb[j].x + comb[j].y*comb[j].y;
        for (int off = 16; off; off >>= 1) {
            sm += __shfl_xor_sync(0xffffffffu, sm, off);
            sq += __shfl_xor_sync(0xffffffffu, sq, off);
        }
        float mean = sm * (1.f/64.f);
        float var  = sq * (1.f/64.f) - mean*mean;
        float ri = rsqrtf(var + 1e-5f);
        float2 lw = *(const float2*)&s_lnw[jj*64 + 2*fp];
        float2 lb = *(const float2*)&s_lnb[jj*64 + 2*fp];
        float2 xn;
        xn.x = (comb[j].x - mean) * ri * lw.x + lb.x;
        xn.y = (comb[j].y - mean) * ri * lw.y + lb.y;
        size_t o = (((size_t)(b*8+jj))*SEQ + s)*64 + 2*fp;
        *(float2*)&g_comb[o] = comb[j];
        *(float2*)&g_xn[o] = xn;
    }
}

// ---------------- K_proj ----------------
__global__ void k_proj(float* __restrict__ out, const float* __restrict__ W2s,
                       const float* __restrict__ bsb) {
    int bx = blockIdx.x;
    int j = bx >> 5, rt = bx & 31;
    int tid = threadIdx.x;
    __shared__ float Wsh[64][64];
    __shared__ float Xsh[64][64];
    const float* W2 = W2s + (size_t)j * 4096;
    for (int t = tid; t < 1024; t += 256)
        ((float4*)Wsh)[t] = ((const float4*)W2)[t];
    for (int t = tid; t < 1024; t += 256) {
        int r = t >> 4, c = t & 15;
        int rg2 = rt*64 + r; int b = rg2 >> 8, s = rg2 & 255;
        ((float4*)&Xsh[r][0])[c] =
            *(const float4*)&g_xn[(((size_t)(b*8+j))*SEQ + s)*64 + c*4];
    }
    __syncthreads();

    int c2 = tid & 31, rg = tid >> 5;
    int c0 = c2 * 2;
    float acc[8][2];
    #pragma unroll
    for (int r = 0; r < 8; r++) { acc[r][0] = 0.f; acc[r][1] = 0.f; }
    #pragma unroll 4
    for (int k = 0; k < 64; k++) {
        float2 wv = *(float2*)&Wsh[k][c0];
        #pragma unroll
        for (int r = 0; r < 8; r++) {
            float xv = Xsh[rg*8 + r][k];
            acc[r][0] = fmaf(xv, wv.x, acc[r][0]);
            acc[r][1] = fmaf(xv, wv.y, acc[r][1]);
        }
    }
    #pragma unroll
    for (int r = 0; r < 8; r++) {
        int rg2 = rt*64 + rg*8 + r; int b = rg2 >> 8, s = rg2 & 255;
        size_t o = OFF_PROJ + (((size_t)(b*8+j))*SEQ + s)*64;
        float2 bv = *(const float2*)&bsb[((size_t)j*SEQ + s)*64 + c0];
        float2 ov; ov.x = acc[r][0] + bv.x; ov.y = acc[r][1] + bv.y;
        *(float2*)&out[o + c0] = ov;
    }
}

// ---------------- K_spatial: attn copy + mma + conv + epilogue ----------------
#define SP_P 258
#define SP_SMEM ((32+64)*SP_P*2 + 64*KSZ*4)
__global__ void __launch_bounds__(256, 2) k_spatial(
        float* __restrict__ out, const float* __restrict__ convk,
        const float* __restrict__ thetas, const float* __restrict__ gammas) {
    extern __shared__ __half sp[];
    __half* sA = sp;
    __half* sB = sp + 32*SP_P;
    float* s_ck = (float*)(sp + 96*SP_P);
    int blk = blockIdx.x;
    int jb = blk >> 3;
    int s0 = (blk & 7) * 32;
    int j = jb >> 3, b = jb & 7;
    int bj = b*8 + j;
    int tid = threadIdx.x;

    for (int t = tid; t < 64*KSZ; t += 256)
        s_ck[t] = convk[j*64*KSZ + t];

    const float* XP = out + OFF_PROJ + (size_t)bj * SEQ * FEAT;
    for (int idx = tid; idx < SEQ*FEAT; idx += 256) {
        int t = idx >> 6, f = idx & 63;
        sB[f*SP_P + t] = __float2half_rn(XP[idx]);
    }
    const __half* Rg = g_rawh + (size_t)jb * SEQ * SEQ + (size_t)s0 * 256;
    for (int idx = tid; idx < 32*128; idx += 256) {
        int r = idx >> 7, c2 = idx & 127;
        *(__half2*)&sA[r*SP_P + c2*2] = *(const __half2*)&Rg[r*256 + c2*2];
    }
    __syncthreads();

    int wid = tid >> 5, lane = tid & 31;
    int wm = (wid & 1) * 16, wn = (wid >> 1) * 16;
    int gr = lane >> 2, tg = lane & 3;
    float acc[2][4];
    #pragma unroll
    for (int n = 0; n < 2; n++)
        #pragma unroll
        for (int q = 0; q < 4; q++) acc[n][q] = 0.f;

    #pragma unroll
    for (int ks = 0; ks < 16; ks++) {
        int kk = ks * 16;
        uint32_t a[4];
        int r = wm + gr;
        a[0] = *(const uint32_t*)&sA[r*SP_P + kk + 2*tg];
        a[1] = *(const uint32_t*)&sA[(r+8)*SP_P + kk + 2*tg];
        a[2] = *(const uint32_t*)&sA[r*SP_P + kk + 8 + 2*tg];
        a[3] = *(const uint32_t*)&sA[(r+8)*SP_P + kk + 8 + 2*tg];
        #pragma unroll
        for (int n = 0; n < 2; n++) {
            int cc = wn + n*8 + gr;
            uint32_t b0 = *(const uint32_t*)&sB[cc*SP_P + kk + 2*tg];
            uint32_t b1 = *(const uint32_t*)&sB[cc*SP_P + kk + 8 + 2*tg];
            asm volatile(
                "mma.sync.aligned.m16n8k16.row.col.f32.f16.f16.f32 "
                "{%0,%1,%2,%3}, {%4,%5,%6,%7}, {%8,%9}, {%0,%1,%2,%3};"
                : "+f"(acc[n][0]), "+f"(acc[n][1]), "+f"(acc[n][2]), "+f"(acc[n][3])
                : "r"(a[0]), "r"(a[1]), "r"(a[2]), "r"(a[3]), "r"(b0), "r"(b1));
        }
    }

    float th = fabsf(thetas[j]);
    float ga = gammas[j];
    #pragma unroll
    for (int n = 0; n < 2; n++) {
        #pragma unroll
        for (int h = 0; h < 2; h++) {
            int s = s0 + wm + gr + h*8;
            #pragma unroll
            for (int cp = 0; cp < 2; cp++) {
                int c = wn + n*8 + 2*tg + cp;
                float v = acc[n][h*2 + cp];
                float w3 = 0.f;
                #pragma unroll
                for (int k = 0; k < KSZ; k++) {
                    int tt = s + k - 7;
                    if (tt >= 0 && tt < SEQ)
                        w3 = fmaf(__half2float(sB[c*SP_P + tt]), s_ck[c*KSZ + k], w3);
                }
                v += th*w3 + ga * g_comb[((size_t)bj*SEQ + s)*64 + c];
                out[((size_t)bj*SEQ + s)*64 + c] = v;
            }
        }
    }
}

// ---------------- launch ----------------
extern "C" void kernel_launch(void* const* d_in, const int* in_sizes, int n_in,
                              void* d_out, int out_size) {
    const float* x_in   = (const float*)d_in[0];
    const float* proj   = (const float*)d_in[1];
    const float* sw     = (const float*)d_in[3];
    const float* tau    = (const float*)d_in[4];
    const float* temp   = (const float*)d_in[5];
    const float* omiga  = (const float*)d_in[6];
    const float* W2s    = (const float*)d_in[7];
    const float* bs     = (const float*)d_in[8];
    const float* ln_w   = (const float*)d_in[9];
    const float* ln_b   = (const float*)d_in[10];
    const float* alphas = (const float*)d_in[11];
    const float* betas  = (const float*)d_in[12];
    const float* thetas = (const float*)d_in[13];
    const float* gammas = (const float*)d_in[14];
    const float* convk  = (const float*)d_in[15];
    float* out = (float*)d_out;

    cudaFuncSetAttribute(k_spatial, cudaFuncAttributeMaxDynamicSharedMemorySize, SP_SMEM);

    k_H      <<<Bb*16, 256>>>(proj);
    k_statsP <<<128, 256>>>(x_in, proj);
    k_actE   <<<Bb*IN_N*8, 256>>>(x_in, sw, omiga);
    k_attn   <<<Bb*64, 256>>>(tau, temp, alphas, betas);   // slot 4 -> profiled
    k_comb   <<<Bb*256, 128>>>(tau, temp, ln_w, ln_b);
    k_proj   <<<OUT_N*32, 256>>>(out, W2s, bs);
    k_spatial<<<OUT_N*Bb*8, 256, SP_SMEM>>>(out, convk, thetas, gammas);
}

// round 17
// speedup vs baseline: 1.0466x; 1.0466x over previous
#include <cuda_runtime.h>
#include <cuda_fp16.h>
#include <math.h>
#include <stdint.h>

#define Bb 8
#define IN_N 8
#define OUT_N 8
#define SEQ 256
#define FEAT 64
#define NCg 99
#define KSZ 15

// ---------------- scratch ----------------
__device__ float g_mu[Bb*IN_N*FEAT];
__device__ float g_rinv[Bb*IN_N*FEAT];
__device__ float g_epart[Bb*IN_N*8*OUT_N];
__device__ __half g_acth[Bb*IN_N*OUT_N*SEQ*FEAT];   // 16.8 MB
__device__ float g_comb[Bb*OUT_N*SEQ*FEAT];
__device__ float g_xn [Bb*OUT_N*SEQ*FEAT];
__device__ float g_pS [Bb*IN_N*SEQ];
__device__ float g_pS2[Bb*IN_N*SEQ];
__device__ float4 g_lnst[OUT_N*Bb*SEQ];              // {mK, rK, 256*mQ*rQ, rQ}
__device__ float g_H[Bb*4*SEQ*SEQ];                  // 8 MB
__device__ __half g_rawh[OUT_N*Bb*SEQ*SEQ];          // 8 MB

#define OFF_PROJ (Bb*OUT_N*SEQ*FEAT)

// ---------------- helpers ----------------
__device__ __forceinline__ void basis4(float u, float* bv, int* ci) {
    int m = (int)floorf(u);
    #pragma unroll
    for (int k = 0; k < 4; k++) {
        int c = m - 1 + k;
        float val = 0.f;
        if (c >= 0 && c < NCg) {
            float d  = fabsf(u - (float)c);
            float r2 = fmaxf(2.f - d, 0.f);
            float r1 = fmaxf(1.f - d, 0.f);
            val = r2*r2*r2*(1.f/6.f) - r1*r1*r1*(4.f/6.f);
        }
        ci[k] = min(max(c, 0), NCg - 1);
        bv[k] = val;
    }
}
__device__ __forceinline__ void maskmult(int bi, int o, const float* tau, float tv,
                                         float* mask, float* mult) {
    float e = 0.f;
    #pragma unroll
    for (int st = 0; st < 8; st++) e += g_epart[(bi*8+st)*8+o];
    float es = sqrtf(e * (1.f/16384.f) + 1e-8f);
    float ta = fabsf(tau[(bi & 7) * 8 + o]);
    *mask = 1.f / (1.f + expf(-(es - ta) / tv));
    *mult = es / (ta + 1e-8f);
}

// ---------------- K_statsP: x stats (bx<64) + proj row sums (bx>=64) ----------------
__global__ void k_statsP(const float* __restrict__ x, const float* __restrict__ proj) {
    int bx = blockIdx.x, tid = threadIdx.x;
    if (bx < 64) {
        int f = tid & 63, q = tid >> 6;
        const float* p = x + (size_t)bx * SEQ * FEAT;
        float s = 0.f, s2 = 0.f;
        for (int t = q*64; t < q*64+64; t++) { float v = p[t*64+f]; s += v; s2 = fmaf(v,v,s2); }
        __shared__ float ps[4][64], ps2[4][64];
        ps[q][f] = s; ps2[q][f] = s2; __syncthreads();
        if (q == 0) {
            float S  = ps[0][f]+ps[1][f]+ps[2][f]+ps[3][f];
            float S2 = ps2[0][f]+ps2[1][f]+ps2[2][f]+ps2[3][f];
            float mu = S * (1.f/256.f);
            float var = S2 * (1.f/256.f) - mu*mu;
            g_mu[bx*64+f] = mu;
            g_rinv[bx*64+f] = rsqrtf(var + 1e-5f);
        }
    } else {
        int bi = bx - 64;
        int w = tid >> 5, lane = tid & 31;
        const float* p = proj + (size_t)bi * SEQ * FEAT;
        for (int r = 0; r < 32; r++) {
            int s = w*32 + r;
            float2 v = *(const float2*)&p[(size_t)s*64 + lane*2];
            float sm = v.x + v.y, sq = v.x*v.x + v.y*v.y;
            for (int off = 16; off; off >>= 1) {
                sm += __shfl_xor_sync(0xffffffffu, sm, off);
                sq += __shfl_xor_sync(0xffffffffu, sq, off);
            }
            if (lane == 0) { g_pS[bi*256+s] = sm; g_pS2[bi*256+s] = sq; }
        }
    }
}

// ---------------- K_actE ----------------
__global__ void k_actE(const float* __restrict__ x, const float* __restrict__ sw,
                       const float* __restrict__ omiga) {
    int bx = blockIdx.x;
    int bi = bx >> 3, st = bx & 7, i = bi & 7;
    int tid = threadIdx.x;
    __shared__ float s_swT[NCg*8];
    __shared__ float s_om[8];
    __shared__ float s_mu[64], s_ri[64];
    __shared__ float wr[8][8];
    for (int t = tid; t < NCg*8; t += 256) {
        int c = t >> 3, o = t & 7;
        s_swT[t] = sw[i*OUT_N*NCg + o*NCg + c];
    }
    if (tid < 8) s_om[tid] = fabsf(omiga[i*8 + tid]);
    if (tid < 64) { s_mu[tid] = g_mu[bi*64+tid]; s_ri[tid] = g_rinv[bi*64+tid]; }
    __syncthreads();

    float eacc[8];
    #pragma unroll
    for (int o = 0; o < 8; o++) eacc[o] = 0.f;

    const float* xb = x + (size_t)bi * SEQ * FEAT + (size_t)st * 32 * FEAT;
    __half* ah = g_acth + (size_t)bi * OUT_N * SEQ * FEAT + (size_t)st * 32 * FEAT;
    #pragma unroll
    for (int it = 0; it < 4; it++) {
        int e = 2*tid + 512*it;
        int ff = e & 63;
        float2 xv = *(const float2*)&xb[e];
        float a0[8], a1[8];
        {
            float xn = (xv.x - s_mu[ff]) * s_ri[ff] * 0.5f;
            xn = fminf(fmaxf(xn, -0.99f), 0.99f);
            float bv[4]; int ci[4];
            basis4((xn + 1.f) * 49.f, bv, ci);
            #pragma unroll
            for (int o = 0; o < 8; o++) a0[o] = s_om[o] * xv.x;
            #pragma unroll
            for (int k = 0; k < 4; k++) {
                float4 w0 = *(const float4*)&s_swT[ci[k]*8];
                float4 w1 = *(const float4*)&s_swT[ci[k]*8 + 4];
                a0[0]=fmaf(bv[k],w0.x,a0[0]); a0[1]=fmaf(bv[k],w0.y,a0[1]);
                a0[2]=fmaf(bv[k],w0.z,a0[2]); a0[3]=fmaf(bv[k],w0.w,a0[3]);
                a0[4]=fmaf(bv[k],w1.x,a0[4]); a0[5]=fmaf(bv[k],w1.y,a0[5]);
                a0[6]=fmaf(bv[k],w1.z,a0[6]); a0[7]=fmaf(bv[k],w1.w,a0[7]);
            }
        }
        {
            float xn = (xv.y - s_mu[ff+1]) * s_ri[ff+1] * 0.5f;
            xn = fminf(fmaxf(xn, -0.99f), 0.99f);
            float bv[4]; int ci[4];
            basis4((xn + 1.f) * 49.f, bv, ci);
            #pragma unroll
            for (int o = 0; o < 8; o++) a1[o] = s_om[o] * xv.y;
            #pragma unroll
            for (int k = 0; k < 4; k++) {
                float4 w0 = *(const float4*)&s_swT[ci[k]*8];
                float4 w1 = *(const float4*)&s_swT[ci[k]*8 + 4];
                a1[0]=fmaf(bv[k],w0.x,a1[0]); a1[1]=fmaf(bv[k],w0.y,a1[1]);
                a1[2]=fmaf(bv[k],w0.z,a1[2]); a1[3]=fmaf(bv[k],w0.w,a1[3]);
                a1[4]=fmaf(bv[k],w1.x,a1[4]); a1[5]=fmaf(bv[k],w1.y,a1[5]);
                a1[6]=fmaf(bv[k],w1.z,a1[6]); a1[7]=fmaf(bv[k],w1.w,a1[7]);
            }
        }
        #pragma unroll
        for (int o = 0; o < 8; o++) {
            eacc[o] = fmaf(a0[o], a0[o], fmaf(a1[o], a1[o], eacc[o]));
            *(__half2*)&ah[(size_t)o * SEQ * FEAT + e] = __floats2half2_rn(a0[o], a1[o]);
        }
    }
    #pragma unroll
    for (int o = 0; o < 8; o++)
        for (int off = 16; off; off >>= 1)
            eacc[o] += __shfl_xor_sync(0xffffffffu, eacc[o], off);
    int w = tid >> 5, lane = tid & 31;
    if (lane == 0)
        for (int o = 0; o < 8; o++) wr[w][o] = eacc[o];
    __syncthreads();
    if (tid < 8) {
        float sm = 0.f;
        for (int ww = 0; ww < 8; ww++) sm += wr[ww][tid];
        g_epart[bx*8 + tid] = sm;
    }
}

// ---------------- K_Hln: bx<128 -> H GEMM; bx>=128 -> LN stats ----------------
#define HPAD 72
__global__ void __launch_bounds__(256) k_Hln(const float* __restrict__ proj,
                                             const float* __restrict__ tau,
                                             const float* __restrict__ temp) {
    int bx = blockIdx.x;
    int tid = threadIdx.x;
    if (bx >= 128) {
        // ---- LN stats: one block per jb ----
        int jb = bx - 128;
        int j = jb >> 3, b = jb & 7;
        __shared__ float ssc[8];
        float tv = fabsf(temp[0]) + 1e-4f;
        if (tid < 8) {
            float mk, ml;
            maskmult(b*8 + tid, j, tau, tv, &mk, &ml);
            ssc[tid] = mk * ml;
        }
        __syncthreads();
        int s = tid;
        float mK = 0.f, sK = 0.f, mQ = 0.f, sQ = 0.f;
        #pragma unroll
        for (int g = 0; g < 4; g++) {
            float cK = ssc[2*g], cQ = ssc[2*g+1];
            int iK = (b*8 + 2*g)*256 + s, iQ = (b*8 + 2*g+1)*256 + s;
            mK = fmaf(cK, g_pS[iK], mK);  sK = fmaf(cK*cK, g_pS2[iK], sK);
            mQ = fmaf(cQ, g_pS[iQ], mQ);  sQ = fmaf(cQ*cQ, g_pS2[iQ], sQ);
        }
        mK *= (1.f/256.f); mQ *= (1.f/256.f);
        float rK = rsqrtf(sK*(1.f/256.f) - mK*mK + 1e-5f);
        float rQ = rsqrtf(sQ*(1.f/256.f) - mQ*mQ + 1e-5f);
        g_lnst[jb*256 + s] = make_float4(mK, rK, 256.f * mQ * rQ, rQ);
        return;
    }
    // ---- H GEMM ----
    __shared__ __half sAH[128*HPAD];
    __shared__ __half sBH[128*HPAD];
    int b = bx >> 4, g = (bx >> 2) & 3, tile = bx & 3;
    int m0 = (tile >> 1)*128, n0 = (tile & 1)*128;
    const float* A  = proj + ((size_t)(b*8 + 2*g  ))*SEQ*FEAT;
    const float* Bp = proj + ((size_t)(b*8 + 2*g+1))*SEQ*FEAT;
    int wid = tid >> 5, lane = tid & 31;
    #pragma unroll
    for (int l = 0; l < 8; l++) {
        int idx = tid + l*256;
        int row = idx >> 4, c4 = idx & 15;
        float4 va = *(const float4*)&A[(size_t)(m0+row)*FEAT + c4*4];
        *(__half2*)&sAH[row*HPAD + c4*4]     = __floats2half2_rn(va.x, va.y);
        *(__half2*)&sAH[row*HPAD + c4*4 + 2] = __floats2half2_rn(va.z, va.w);
        float4 vb = *(const float4*)&Bp[(size_t)(n0+row)*FEAT + c4*4];
        *(__half2*)&sBH[row*HPAD + c4*4]     = __floats2half2_rn(vb.x, vb.y);
        *(__half2*)&sBH[row*HPAD + c4*4 + 2] = __floats2half2_rn(vb.z, vb.w);
    }
    __syncthreads();

    int wm = (wid & 3)*32, wn = (wid >> 2)*64;
    int gr = lane >> 2, tg = lane & 3;
    float acc[2][8][4];
    #pragma unroll
    for (int i = 0; i < 2; i++)
        #pragma unroll
        for (int n = 0; n < 8; n++)
            #pragma unroll
            for (int q = 0; q < 4; q++) acc[i][n][q] = 0.f;

    #pragma unroll
    for (int ks = 0; ks < 4; ks++) {
        int kk = ks * 16;
        uint32_t a[2][4];
        #pragma unroll
        for (int i = 0; i < 2; i++) {
            int r = wm + i*16 + gr;
            a[i][0] = *(const uint32_t*)&sAH[r*HPAD + kk + 2*tg];
            a[i][1] = *(const uint32_t*)&sAH[(r+8)*HPAD + kk + 2*tg];
            a[i][2] = *(const uint32_t*)&sAH[r*HPAD + kk + 8 + 2*tg];
            a[i][3] = *(const uint32_t*)&sAH[(r+8)*HPAD + kk + 8 + 2*tg];
        }
        uint32_t bfr[8][2];
        #pragma unroll
        for (int n = 0; n < 8; n++) {
            int cc = wn + n*8 + gr;
            bfr[n][0] = *(const uint32_t*)&sBH[cc*HPAD + kk + 2*tg];
            bfr[n][1] = *(const uint32_t*)&sBH[cc*HPAD + kk + 8 + 2*tg];
        }
        #pragma unroll
        for (int i = 0; i < 2; i++)
            #pragma unroll
            for (int n = 0; n < 8; n++) {
                asm volatile(
                    "mma.sync.aligned.m16n8k16.row.col.f32.f16.f16.f32 "
                    "{%0,%1,%2,%3}, {%4,%5,%6,%7}, {%8,%9}, {%0,%1,%2,%3};"
                    : "+f"(acc[i][n][0]), "+f"(acc[i][n][1]),
                      "+f"(acc[i][n][2]), "+f"(acc[i][n][3])
                    : "r"(a[i][0]), "r"(a[i][1]), "r"(a[i][2]), "r"(a[i][3]),
                      "r"(bfr[n][0]), "r"(bfr[n][1]));
            }
    }
    float* Hg = g_H + ((size_t)(b*4+g))*SEQ*SEQ;
    #pragma unroll
    for (int i = 0; i < 2; i++)
        #pragma unroll
        for (int n = 0; n < 8; n++) {
            int r = m0 + wm + i*16 + gr;
            int c = n0 + wn + n*8 + 2*tg;
            float2 o0 = {acc[i][n][0], acc[i][n][1]};
            float2 o1 = {acc[i][n][2], acc[i][n][3]};
            *(float2*)&Hg[(size_t)r*256 + c]     = o0;
            *(float2*)&Hg[(size_t)(r+8)*256 + c] = o1;
        }
}

// ---------------- K_attn: raw-from-H (read once) + softmax, stats precomputed ----------------
__global__ void __launch_bounds__(256) k_attn(const float* __restrict__ tau,
                                              const float* __restrict__ temp,
                                              const float* __restrict__ alphas,
                                              const float* __restrict__ betas) {
    int bx = blockIdx.x;            // b*32 + tile(8 rows)
    int b = bx >> 5, s0 = (bx & 31) * 8;
    int tid = threadIdx.x;
    __shared__ float s_sc[8][8];
    __shared__ float s_w[8][4];
    __shared__ float s_mQ[8][264], s_rQ[8][264];   // mQ holds 256*mQ*rQ; rQ holds rQ
    __shared__ float s_mk[8][8], s_rk[8][8];
    __shared__ float s_be[8], s_al[8];

    float tv = fabsf(temp[0]) + 1e-4f;
    if (tid < 64) {
        float mk, ml;
        maskmult(b*8 + (tid>>3), tid & 7, tau, tv, &mk, &ml);
        s_sc[tid>>3][tid&7] = mk * ml;
    }
    if (tid < 8) { s_be[tid] = fabsf(betas[tid]); s_al[tid] = fabsf(alphas[tid]); }
    __syncthreads();
    if (tid < 32) {
        int j = tid >> 2, g = tid & 3;
        s_w[j][g] = s_sc[2*g][j] * s_sc[2*g+1][j];
    }
    for (int t = tid; t < 2048; t += 256) {
        int j = t >> 8, tt = t & 255;
        float4 l = g_lnst[(j*8 + b)*256 + tt];
        int ti = tt + (tt >> 5);
        s_mQ[j][ti] = l.z;
        s_rQ[j][ti] = l.w;
        if (tt >= s0 && tt < s0 + 8) { s_mk[j][tt-s0] = l.x; s_rk[j][tt-s0] = l.y; }
    }
    __syncthreads();

    int row = tid >> 5, lane = tid & 31;
    int tbase = lane * 8;
    float h[4][8];
    const float* Hb = g_H + (size_t)b*4*65536 + (size_t)(s0+row)*256 + tbase;
    #pragma unroll
    for (int g = 0; g < 4; g++) {
        float4 v0 = *(const float4*)&Hb[(size_t)g*65536];
        float4 v1 = *(const float4*)&Hb[(size_t)g*65536 + 4];
        h[g][0]=v0.x; h[g][1]=v0.y; h[g][2]=v0.z; h[g][3]=v0.w;
        h[g][4]=v1.x; h[g][5]=v1.y; h[g][6]=v1.z; h[g][7]=v1.w;
    }
    float inv = 1.f / (16.f * tv);
    int lq = lane >> 2;
    #pragma unroll
    for (int j = 0; j < 8; j++) {
        float w0 = s_w[j][0], w1 = s_w[j][1], w2 = s_w[j][2], w3 = s_w[j][3];
        float mK = s_mk[j][row];
        float rKi = s_rk[j][row] * inv;
        float raw[8];
        float m = -1e30f;
        #pragma unroll
        for (int e = 0; e < 8; e++) {
            int ti = tbase + e + lq;
            float hs = w0*h[0][e] + w1*h[1][e] + w2*h[2][e] + w3*h[3][e];
            float r = (hs * s_rQ[j][ti] - mK * s_mQ[j][ti]) * rKi;
            raw[e] = r;
            m = fmaxf(m, r);
        }
        for (int off = 16; off; off >>= 1) m = fmaxf(m, __shfl_xor_sync(0xffffffffu, m, off));
        float sum = 0.f;
        #pragma unroll
        for (int e = 0; e < 8; e++) { raw[e] = __expf(raw[e] - m); sum += raw[e]; }
        for (int off = 16; off; off >>= 1) sum += __shfl_xor_sync(0xffffffffu, sum, off);
        float sc2 = s_be[j] / sum;
        float al = s_al[j];
        __half2 hv[4];
        #pragma unroll
        for (int e2 = 0; e2 < 4; e2++) {
            float va = raw[2*e2] * sc2;
            float vb = raw[2*e2+1] * sc2;
            int t0 = tbase + 2*e2;
            if (t0     == s0 + row) va += al;
            if (t0 + 1 == s0 + row) vb += al;
            hv[e2] = __floats2half2_rn(va, vb);
        }
        *(uint4*)&g_rawh[((size_t)(j*8+b))*65536 + (size_t)(s0+row)*256 + tbase] = *(uint4*)hv;
    }
}

// ---------------- K_comb ----------------
__global__ void k_comb(const float* __restrict__ tau, const float* __restrict__ temp,
                       const float* __restrict__ ln_w, const float* __restrict__ ln_b) {
    int bx = blockIdx.x;
    int b = bx >> 8;
    int rem = bx & 255;
    int st = rem >> 2, jh = (rem & 3) * 2;
    int tid = threadIdx.x;
    int fp = tid & 31;
    int sl = tid >> 5;
    int s = st*4 + sl;
    __shared__ float s_mask[8][8];
    __shared__ float s_lnw[512], s_lnb[512];

    float tv = fabsf(temp[0]) + 1e-4f;
    if (tid < 64) {
        float mk, ml;
        maskmult(b*8 + (tid>>3), tid & 7, tau, tv, &mk, &ml);
        s_mask[tid>>3][tid&7] = mk;
    }
    for (int t = tid; t < 512; t += 128) { s_lnw[t] = ln_w[t]; s_lnb[t] = ln_b[t]; }
    __syncthreads();

    float2 comb[2];
    #pragma unroll
    for (int j = 0; j < 2; j++) { comb[j].x = 0.f; comb[j].y = 0.f; }

    size_t ebase = (size_t)s * 64 + 2*fp;
    #pragma unroll
    for (int i = 0; i < 8; i++) {
        const __half* ai = g_acth + ((size_t)(b*8+i)) * OUT_N * SEQ * FEAT
                         + (size_t)jh * SEQ * FEAT;
        #pragma unroll
        for (int j = 0; j < 2; j++) {
            float2 v = __half22float2(*(const __half2*)&ai[(size_t)j*SEQ*FEAT + ebase]);
            float mk = s_mask[i][jh + j];
            comb[j].x = fmaf(mk, v.x, comb[j].x);
            comb[j].y = fmaf(mk, v.y, comb[j].y);
        }
    }

    #pragma unroll
    for (int j = 0; j < 2; j++) {
        int jj = jh + j;
        float sm = comb[j].x + comb[j].y;
        float sq = comb[j].x*comb[j].x + comb[j].y*comb[j].y;
        for (int off = 16; off; off >>= 1) {
            sm += __shfl_xor_sync(0xffffffffu, sm, off);
            sq += __shfl_xor_sync(0xffffffffu, sq, off);
        }
        float mean = sm * (1.f/64.f);
        float var  = sq * (1.f/64.f) - mean*mean;
        float ri = rsqrtf(var + 1e-5f);
        float2 lw = *(const float2*)&s_lnw[jj*64 + 2*fp];
        float2 lb = *(const float2*)&s_lnb[jj*64 + 2*fp];
        float2 xn;
        xn.x = (comb[j].x - mean) * ri * lw.x + lb.x;
        xn.y = (comb[j].y - mean) * ri * lw.y + lb.y;
        size_t o = (((size_t)(b*8+jj))*SEQ + s)*64 + 2*fp;
        *(float2*)&g_comb[o] = comb[j];
        *(float2*)&g_xn[o] = xn;
    }
}

// ---------------- K_proj ----------------
__global__ void k_proj(float* __restrict__ out, const float* __restrict__ W2s,
                       const float* __restrict__ bsb) {
    int bx = blockIdx.x;
    int j = bx >> 5, rt = bx & 31;
    int tid = threadIdx.x;
    __shared__ float Wsh[64][64];
    __shared__ float Xsh[64][64];
    const float* W2 = W2s + (size_t)j * 4096;
    for (int t = tid; t < 1024; t += 256)
        ((float4*)Wsh)[t] = ((const float4*)W2)[t];
    for (int t = tid; t < 1024; t += 256) {
        int r = t >> 4, c = t & 15;
        int rg2 = rt*64 + r; int b = rg2 >> 8, s = rg2 & 255;
        ((float4*)&Xsh[r][0])[c] =
            *(const float4*)&g_xn[(((size_t)(b*8+j))*SEQ + s)*64 + c*4];
    }
    __syncthreads();

    int c2 = tid & 31, rg = tid >> 5;
    int c0 = c2 * 2;
    float acc[8][2];
    #pragma unroll
    for (int r = 0; r < 8; r++) { acc[r][0] = 0.f; acc[r][1] = 0.f; }
    #pragma unroll 4
    for (int k = 0; k < 64; k++) {
        float2 wv = *(float2*)&Wsh[k][c0];
        #pragma unroll
        for (int r = 0; r < 8; r++) {
            float xv = Xsh[rg*8 + r][k];
            acc[r][0] = fmaf(xv, wv.x, acc[r][0]);
            acc[r][1] = fmaf(xv, wv.y, acc[r][1]);
        }
    }
    #pragma unroll
    for (int r = 0; r < 8; r++) {
        int rg2 = rt*64 + rg*8 + r; int b = rg2 >> 8, s = rg2 & 255;
        size_t o = OFF_PROJ + (((size_t)(b*8+j))*SEQ + s)*64;
        float2 bv = *(const float2*)&bsb[((size_t)j*SEQ + s)*64 + c0];
        float2 ov; ov.x = acc[r][0] + bv.x; ov.y = acc[r][1] + bv.y;
        *(float2*)&out[o + c0] = ov;
    }
}

// ---------------- K_spatial: attn copy + mma + conv + epilogue ----------------
#define SP_P 258
#define SP_SMEM ((32+64)*SP_P*2 + 64*KSZ*4)
__global__ void __launch_bounds__(256, 2) k_spatial(
        float* __restrict__ out, const float* __restrict__ convk,
        const float* __restrict__ thetas, const float* __restrict__ gammas) {
    extern __shared__ __half sp[];
    __half* sA = sp;
    __half* sB = sp + 32*SP_P;
    float* s_ck = (float*)(sp + 96*SP_P);
    int blk = blockIdx.x;
    int jb = blk >> 3;
    int s0 = (blk & 7) * 32;
    int j = jb >> 3, b = jb & 7;
    int bj = b*8 + j;
    int tid = threadIdx.x;

    for (int t = tid; t < 64*KSZ; t += 256)
        s_ck[t] = convk[j*64*KSZ + t];

    const float* XP = out + OFF_PROJ + (size_t)bj * SEQ * FEAT;
    for (int idx = tid; idx < SEQ*FEAT; idx += 256) {
        int t = idx >> 6, f = idx & 63;
        sB[f*SP_P + t] = __float2half_rn(XP[idx]);
    }
    const __half* Rg = g_rawh + (size_t)jb * SEQ * SEQ + (size_t)s0 * 256;
    for (int idx = tid; idx < 32*128; idx += 256) {
        int r = idx >> 7, c2 = idx & 127;
        *(__half2*)&sA[r*SP_P + c2*2] = *(const __half2*)&Rg[r*256 + c2*2];
    }
    __syncthreads();

    int wid = tid >> 5, lane = tid & 31;
    int wm = (wid & 1) * 16, wn = (wid >> 1) * 16;
    int gr = lane >> 2, tg = lane & 3;
    float acc[2][4];
    #pragma unroll
    for (int n = 0; n < 2; n++)
        #pragma unroll
        for (int q = 0; q < 4; q++) acc[n][q] = 0.f;

    #pragma unroll
    for (int ks = 0; ks < 16; ks++) {
        int kk = ks * 16;
        uint32_t a[4];
        int r = wm + gr;
        a[0] = *(const uint32_t*)&sA[r*SP_P + kk + 2*tg];
        a[1] = *(const uint32_t*)&sA[(r+8)*SP_P + kk + 2*tg];
        a[2] = *(const uint32_t*)&sA[r*SP_P + kk + 8 + 2*tg];
        a[3] = *(const uint32_t*)&sA[(r+8)*SP_P + kk + 8 + 2*tg];
        #pragma unroll
        for (int n = 0; n < 2; n++) {
            int cc = wn + n*8 + gr;
            uint32_t b0 = *(const uint32_t*)&sB[cc*SP_P + kk + 2*tg];
            uint32_t b1 = *(const uint32_t*)&sB[cc*SP_P + kk + 8 + 2*tg];
            asm volatile(
                "mma.sync.aligned.m16n8k16.row.col.f32.f16.f16.f32 "
                "{%0,%1,%2,%3}, {%4,%5,%6,%7}, {%8,%9}, {%0,%1,%2,%3};"
                : "+f"(acc[n][0]), "+f"(acc[n][1]), "+f"(acc[n][2]), "+f"(acc[n][3])
                : "r"(a[0]), "r"(a[1]), "r"(a[2]), "r"(a[3]), "r"(b0), "r"(b1));
        }
    }

    float th = fabsf(thetas[j]);
    float ga = gammas[j];
    #pragma unroll
    for (int n = 0; n < 2; n++) {
        #pragma unroll
        for (int h = 0; h < 2; h++) {
            int s = s0 + wm + gr + h*8;
            #pragma unroll
            for (int cp = 0; cp < 2; cp++) {
                int c = wn + n*8 + 2*tg + cp;
                float v = acc[n][h*2 + cp];
                float w3 = 0.f;
                #pragma unroll
                for (int k = 0; k < KSZ; k++) {
                    int tt = s + k - 7;
                    if (tt >= 0 && tt < SEQ)
                        w3 = fmaf(__half2float(sB[c*SP_P + tt]), s_ck[c*KSZ + k], w3);
                }
                v += th*w3 + ga * g_comb[((size_t)bj*SEQ + s)*64 + c];
                out[((size_t)bj*SEQ + s)*64 + c] = v;
            }
        }
    }
}

// ---------------- launch ----------------
extern "C" void kernel_launch(void* const* d_in, const int* in_sizes, int n_in,
                              void* d_out, int out_size) {
    const float* x_in   = (const float*)d_in[0];
    const float* proj   = (const float*)d_in[1];
    const float* sw     = (const float*)d_in[3];
    const float* tau    = (const float*)d_in[4];
    const float* temp   = (const float*)d_in[5];
    const float* omiga  = (const float*)d_in[6];
    const float* W2s    = (const float*)d_in[7];
    const float* bs     = (const float*)d_in[8];
    const float* ln_w   = (const float*)d_in[9];
    const float* ln_b   = (const float*)d_in[10];
    const float* alphas = (const float*)d_in[11];
    const float* betas  = (const float*)d_in[12];
    const float* thetas = (const float*)d_in[13];
    const float* gammas = (const float*)d_in[14];
    const float* convk  = (const float*)d_in[15];
    float* out = (float*)d_out;

    cudaFuncSetAttribute(k_spatial, cudaFuncAttributeMaxDynamicSharedMemorySize, SP_SMEM);

    k_statsP <<<128, 256>>>(x_in, proj);
    k_actE   <<<Bb*IN_N*8, 256>>>(x_in, sw, omiga);
    k_Hln    <<<128 + OUT_N*Bb, 256>>>(proj, tau, temp);
    k_attn   <<<Bb*32, 256>>>(tau, temp, alphas, betas);   // slot 4 -> profiled
    k_comb   <<<Bb*256, 128>>>(tau, temp, ln_w, ln_b);
    k_proj   <<<OUT_N*32, 256>>>(out, W2s, bs);
    k_spatial<<<OUT_N*Bb*8, 256, SP_SMEM>>>(out, convk, thetas, gammas);
}